// round 6
// baseline (speedup 1.0000x reference)
#include <cuda_runtime.h>
#include <cstdint>

#define RES   64
#define CH    8
#define NB    64
#define CORE  32
#define POS   16
#define DIMSZ (CORE*CORE*CORE*CH)   // 262144
#define BATCH 32

#define BGROUPS 4                   // 4 batch groups of 8
#define BPG     8                   // batches per thread
#define DPT     8                   // dims per thread
#define COMPUTE_BLOCKS (DIMSZ / (256 * DPT) * BGROUPS)  // 128*4 = 512

// Zero-fill: block = (b, ch, i-chunk of 16 planes). 32*8*4 = 1024 blocks.
#define I_CHUNK 16
#define ZERO_BLOCKS (BATCH * CH * (RES / I_CHUNK))      // 1024
#define GRID (COMPUTE_BLOCKS + ZERO_BLOCKS)

__global__ void __launch_bounds__(256, 2) core_subspace_fused(
    const float* __restrict__ z,   // (32, 64)
    const float* __restrict__ U,   // (64, 262144)
    const float* __restrict__ L,   // (64,)
    const float* __restrict__ mu,  // (262144,)
    float* __restrict__ out)       // (32, 8, 64, 64, 64)
{
    const int tid = threadIdx.x;

    if (blockIdx.x >= COMPUTE_BLOCKS) {
        // ------------- periphery zero-fill: slab per (b, ch, i-chunk) -------
        // Each thread owns 4 fixed (j, w4) positions in the 64x16-float4 plane;
        // the row predicate is hoisted out of the i loop.
        const int zb  = blockIdx.x - COMPUTE_BLOCKS;        // 0..1023
        const int ic  = zb & 3;                              // i-chunk
        const int bc  = zb >> 2;                             // b*8 + ch
        const int i0  = ic * I_CHUNK;

        bool row_core[4];
#pragma unroll
        for (int c = 0; c < 4; c++) {
            const int fl = c * 256 + tid;                    // 0..1023
            const unsigned w4 = fl & 15;
            const unsigned j  = fl >> 4;
            row_core[c] = (j - 16u < 32u) & (w4 - 4u < 8u);
        }

        const float4 zero4 = make_float4(0.f, 0.f, 0.f, 0.f);
        float4* p = reinterpret_cast<float4*>(out)
                  + (size_t)bc * (RES * RES * RES / 4)
                  + (size_t)i0 * (RES * RES / 4);

#pragma unroll 4
        for (int ii = 0; ii < I_CHUNK; ii++) {
            const bool icore = ((unsigned)(i0 + ii) - 16u) < 32u;
#pragma unroll
            for (int c = 0; c < 4; c++) {
                if (!(icore && row_core[c]))
                    __stcs(&p[c * 256 + tid], zero4);
            }
            p += RES * RES / 4;    // next i-plane (1024 float4)
        }
        return;
    }

    // ---------------- GEMM + scatter ----------------
    // zL packed as duplicated-f32x2 pairs; one LDS.128 broadcast feeds 8 FFMA2.
    __shared__ alignas(16) unsigned long long s_zl[BATCH * NB];  // 16 KB

    for (int idx = tid; idx < BATCH * NB; idx += 256) {
        float v = L[idx & (NB - 1)] * z[idx];
        unsigned int vb = __float_as_uint(v);
        unsigned long long p;
        asm("mov.b64 %0, {%1, %1};" : "=l"(p) : "r"(vb));
        s_zl[idx] = p;
    }
    __syncthreads();

    // Group-minor: 4 blocks sharing a dim-chunk run concurrently -> U re-reads
    // hit L2 (whole U = 67MB fits in 126MB L2).
    const int bg       = blockIdx.x & (BGROUPS - 1);
    const int dimchunk = blockIdx.x >> 2;            // 0..127
    const int b0       = bg * BPG;

    const int d0 = (dimchunk * 256 + tid) * DPT;     // dim index, multiple of 8

    const ulonglong2 mu_a = *reinterpret_cast<const ulonglong2*>(mu + d0);
    const ulonglong2 mu_b = *reinterpret_cast<const ulonglong2*>(mu + d0 + 4);

    unsigned long long acc[BPG][4];
#pragma unroll
    for (int b = 0; b < BPG; b++) {
        acc[b][0] = mu_a.x; acc[b][1] = mu_a.y;
        acc[b][2] = mu_b.x; acc[b][3] = mu_b.y;
    }

    const float* Up = U + d0;
    const ulonglong2* zl2 = reinterpret_cast<const ulonglong2*>(s_zl);

#define LDU(k, off) (*reinterpret_cast<const ulonglong2*>( \
                     Up + (size_t)(k) * DIMSZ + (off)))

    // Software pipeline depth 1: next kp-pair's 4 LDG.128 in flight during FMAs.
    ulonglong2 ua0 = LDU(0, 0), ua1 = LDU(0, 4);   // k = 2*kp
    ulonglong2 ub0 = LDU(1, 0), ub1 = LDU(1, 4);   // k = 2*kp+1

#pragma unroll 2
    for (int kp = 0; kp < NB / 2; kp++) {
        ulonglong2 na0, na1, nb0, nb1;
        if (kp < NB / 2 - 1) {
            na0 = LDU(2 * kp + 2, 0); na1 = LDU(2 * kp + 2, 4);
            nb0 = LDU(2 * kp + 3, 0); nb1 = LDU(2 * kp + 3, 4);
        }
#pragma unroll
        for (int b = 0; b < BPG; b++) {
            const ulonglong2 zz = zl2[(b0 + b) * (NB / 2) + kp];  // LDS.128 bcast
            asm("fma.rn.f32x2 %0, %1, %2, %0;" : "+l"(acc[b][0]) : "l"(ua0.x), "l"(zz.x));
            asm("fma.rn.f32x2 %0, %1, %2, %0;" : "+l"(acc[b][1]) : "l"(ua0.y), "l"(zz.x));
            asm("fma.rn.f32x2 %0, %1, %2, %0;" : "+l"(acc[b][2]) : "l"(ua1.x), "l"(zz.x));
            asm("fma.rn.f32x2 %0, %1, %2, %0;" : "+l"(acc[b][3]) : "l"(ua1.y), "l"(zz.x));
            asm("fma.rn.f32x2 %0, %1, %2, %0;" : "+l"(acc[b][0]) : "l"(ub0.x), "l"(zz.y));
            asm("fma.rn.f32x2 %0, %1, %2, %0;" : "+l"(acc[b][1]) : "l"(ub0.y), "l"(zz.y));
            asm("fma.rn.f32x2 %0, %1, %2, %0;" : "+l"(acc[b][2]) : "l"(ub1.x), "l"(zz.y));
            asm("fma.rn.f32x2 %0, %1, %2, %0;" : "+l"(acc[b][3]) : "l"(ub1.y), "l"(zz.y));
        }
        ua0 = na0; ua1 = na1; ub0 = nb0; ub1 = nb1;
    }
#undef LDU

    // Scatter the 8-dim chunk into the core region (streaming stores).
    // dim = ((c*32 + i)*32 + j)*32 + w ; w = d0&31 in {0,8,16,24} -> 16B aligned
    const int w = d0 & 31;
    const int j = (d0 >> 5) & 31;
    const int i = (d0 >> 10) & 31;
    const int c = d0 >> 15;

    const size_t obase = (size_t)c * (RES * RES * RES)
                       + (size_t)(i + POS) * (RES * RES)
                       + (size_t)(j + POS) * RES
                       + (size_t)(w + POS);

#pragma unroll
    for (int b = 0; b < BPG; b++) {
        float* o = out + (size_t)(b0 + b) * (CH * RES * RES * RES) + obase;
        float4 v0, v1;
        v0.x = __uint_as_float((unsigned)(acc[b][0]));
        v0.y = __uint_as_float((unsigned)(acc[b][0] >> 32));
        v0.z = __uint_as_float((unsigned)(acc[b][1]));
        v0.w = __uint_as_float((unsigned)(acc[b][1] >> 32));
        v1.x = __uint_as_float((unsigned)(acc[b][2]));
        v1.y = __uint_as_float((unsigned)(acc[b][2] >> 32));
        v1.z = __uint_as_float((unsigned)(acc[b][3]));
        v1.w = __uint_as_float((unsigned)(acc[b][3] >> 32));
        __stcs(reinterpret_cast<float4*>(o),     v0);
        __stcs(reinterpret_cast<float4*>(o + 4), v1);
    }
}

extern "C" void kernel_launch(void* const* d_in, const int* in_sizes, int n_in,
                              void* d_out, int out_size)
{
    const float* z  = (const float*)d_in[0];
    const float* U  = (const float*)d_in[1];
    const float* L  = (const float*)d_in[2];
    const float* mu = (const float*)d_in[3];
    float* out = (float*)d_out;

    core_subspace_fused<<<GRID, 256>>>(z, U, L, mu, out);
}